// round 4
// baseline (speedup 1.0000x reference)
#include <cuda_runtime.h>
#include <cuda_bf16.h>
#include <stdint.h>

#define MAX_USERS 100000
#define EMBED 128
#define TILE_M 128

// ---------------------------------------------------------------------------
// Scratch in __device__ globals (no allocation allowed anywhere)
// ---------------------------------------------------------------------------
__device__ float    g_xt[(size_t)MAX_USERS * EMBED];  // x @ W result
__device__ int      g_row_ptr[MAX_USERS + 1];
__device__ uint16_t g_wt[2][2][EMBED * EMBED];        // [layer][hi/lo] W^T bf16, [n][k] row-major

// ---------------------------------------------------------------------------
// SMEM layout for the GEMM: 4 bf16 tiles of 128 rows x 136 bf16 (272 B padded)
//   xh | xl | wh | wl .  272 % 128 = 16 -> 8 consecutive rows hit 8 distinct
//   16B bank-groups, so ldmatrix (8 rows x 16 B) is conflict-free.
// ---------------------------------------------------------------------------
#define ROW_B   272                      // bytes per padded row
#define TILE_B  (128 * ROW_B)            // 34816 B per tile
#define SM_XH   0
#define SM_XL   (TILE_B)
#define SM_WH   (2 * TILE_B)
#define SM_WL   (3 * TILE_B)
#define SM_TOTAL (4 * TILE_B)            // 139264 B

__device__ __forceinline__ uint32_t smem_u32(const void* p) {
    uint32_t a;
    asm("{ .reg .u64 t; cvta.to.shared.u64 t, %1; cvt.u32.u64 %0, t; }" : "=r"(a) : "l"(p));
    return a;
}

#define LDSM_X4(f0, f1, f2, f3, addr) \
    asm volatile("ldmatrix.sync.aligned.m8n8.x4.shared.b16 {%0,%1,%2,%3}, [%4];" \
        : "=r"(f0), "=r"(f1), "=r"(f2), "=r"(f3) : "r"(addr))

#define MMA_BF16(c0, c1, c2, c3, a0, a1, a2, a3, b0, b1) \
    asm volatile("mma.sync.aligned.m16n8k16.row.col.f32.bf16.bf16.f32 " \
        "{%0,%1,%2,%3}, {%4,%5,%6,%7}, {%8,%9}, {%0,%1,%2,%3};" \
        : "+f"(c0), "+f"(c1), "+f"(c2), "+f"(c3) \
        : "r"(a0), "r"(a1), "r"(a2), "r"(a3), "r"(b0), "r"(b1))

// ---------------------------------------------------------------------------
// Prep: W (row-major [k][n]) -> W^T bf16 hi/lo planes in [n][k] order
// ---------------------------------------------------------------------------
__global__ void prep_w_kernel(const float* __restrict__ W0, const float* __restrict__ W1) {
    const float* W = (blockIdx.x == 0) ? W0 : W1;
    uint16_t* dh = g_wt[blockIdx.x][0];
    uint16_t* dl = g_wt[blockIdx.x][1];
    for (int idx = threadIdx.x; idx < EMBED * EMBED; idx += blockDim.x) {
        int k = idx >> 7, n = idx & 127;
        float w = W[idx];
        __nv_bfloat16 h = __float2bfloat16(w);
        __nv_bfloat16 l = __float2bfloat16(w - __bfloat162float(h));
        dh[n * EMBED + k] = *(uint16_t*)&h;
        dl[n * EMBED + k] = *(uint16_t*)&l;
    }
}

// ---------------------------------------------------------------------------
// Build CSR row_ptr from sorted s_rows
// ---------------------------------------------------------------------------
__global__ void build_rowptr_kernel(const int* __restrict__ rows, int E, int M) {
    int e = blockIdx.x * blockDim.x + threadIdx.x;
    if (e >= E) return;
    int r = rows[e];
    if (e == 0) { for (int i = 0; i <= r; i++) g_row_ptr[i] = 0; }
    else { int rp = rows[e - 1]; for (int i = rp + 1; i <= r; i++) g_row_ptr[i] = e; }
    if (e == E - 1) { for (int i = r + 1; i <= M; i++) g_row_ptr[i] = E; }
}

// ---------------------------------------------------------------------------
// HMMA GEMM: Xt = A[M,128] @ W[128,128], fp32-accurate via bf16 hi/lo split:
//   A@W ~= xh@Wh + xh@Wl + xl@Wh   (dropped xl@Wl ~ 2^-16 rel)
// CTA: 256 threads / 8 warps; warp w owns rows w*16..w*16+15, all 128 cols.
// ---------------------------------------------------------------------------
__global__ __launch_bounds__(256) void gemm_hmma_kernel(const float* __restrict__ A,
                                                        int layer,
                                                        float* __restrict__ Xt,
                                                        int M) {
    extern __shared__ char smem[];
    const uint32_t sb = smem_u32(smem);
    const int tid = threadIdx.x;
    const int wid = tid >> 5;
    const int lid = tid & 31;
    const int row0 = blockIdx.x * TILE_M;

    // ---- Stage W^T hi/lo into padded smem: thread t copies half of row n=t>>1
    {
        const uint4* gh = (const uint4*)g_wt[layer][0];
        const uint4* gl = (const uint4*)g_wt[layer][1];
        int n = tid >> 1, h = tid & 1;
        // one row = 256 B = 16 uint4; half = 8 uint4
        uint4* sh = (uint4*)(smem + SM_WH + n * ROW_B + h * 128);
        uint4* sl = (uint4*)(smem + SM_WL + n * ROW_B + h * 128);
        const uint4* srch = gh + n * 16 + h * 8;
        const uint4* srcl = gl + n * 16 + h * 8;
#pragma unroll
        for (int i = 0; i < 8; i++) { sh[i] = srch[i]; sl[i] = srcl[i]; }
    }

    // ---- Stage A rows -> bf16 hi/lo tiles: thread t does row t>>1, half t&1
    {
        int r = tid >> 1, h = tid & 1;
        int grow = row0 + r;
        const float4* src = (grow < M) ? (const float4*)(A + (size_t)grow * EMBED + h * 64) : nullptr;
        uint32_t* dsth = (uint32_t*)(smem + SM_XH + r * ROW_B + h * 128);
        uint32_t* dstl = (uint32_t*)(smem + SM_XL + r * ROW_B + h * 128);
#pragma unroll
        for (int i = 0; i < 16; i++) {
            float4 f = src ? src[i] : make_float4(0.f, 0.f, 0.f, 0.f);
            __nv_bfloat16 h0 = __float2bfloat16(f.x), h1 = __float2bfloat16(f.y);
            __nv_bfloat16 h2 = __float2bfloat16(f.z), h3 = __float2bfloat16(f.w);
            __nv_bfloat16 l0 = __float2bfloat16(f.x - __bfloat162float(h0));
            __nv_bfloat16 l1 = __float2bfloat16(f.y - __bfloat162float(h1));
            __nv_bfloat16 l2 = __float2bfloat16(f.z - __bfloat162float(h2));
            __nv_bfloat16 l3 = __float2bfloat16(f.w - __bfloat162float(h3));
            dsth[2 * i]     = (uint32_t)*(uint16_t*)&h0 | ((uint32_t)*(uint16_t*)&h1 << 16);
            dsth[2 * i + 1] = (uint32_t)*(uint16_t*)&h2 | ((uint32_t)*(uint16_t*)&h3 << 16);
            dstl[2 * i]     = (uint32_t)*(uint16_t*)&l0 | ((uint32_t)*(uint16_t*)&l1 << 16);
            dstl[2 * i + 1] = (uint32_t)*(uint16_t*)&l2 | ((uint32_t)*(uint16_t*)&l3 << 16);
        }
    }
    __syncthreads();

    // ---- ldmatrix per-lane address offsets
    // A frag (m16k16, x4): matrices {m0-7 k0}, {m8-15 k0}, {m0-7 k8}, {m8-15 k8}
    const int a_m = (((lid >> 3) & 1) << 3) + (lid & 7);
    const int a_k = ((lid >> 4) & 1) << 3;
    const uint32_t aoff = (uint32_t)((wid * 16 + a_m) * ROW_B + a_k * 2);
    // B frag (2 n-blocks, x4): {n0-7 k0}, {n0-7 k8}, {n8-15 k0}, {n8-15 k8}
    const int b_n = (((lid >> 4) & 1) << 3) + (lid & 7);
    const int b_k = ((lid >> 3) & 1) << 3;
    const uint32_t boff = (uint32_t)(b_n * ROW_B + b_k * 2);

    float acc[16][4];
#pragma unroll
    for (int nb = 0; nb < 16; nb++)
#pragma unroll
        for (int i = 0; i < 4; i++) acc[nb][i] = 0.f;

#pragma unroll 1
    for (int prod = 0; prod < 3; prod++) {
        const uint32_t abase = sb + (prod == 2 ? SM_XL : SM_XH) + aoff;
        const uint32_t bbase = sb + (prod == 1 ? SM_WL : SM_WH) + boff;
#pragma unroll
        for (int ks = 0; ks < 8; ks++) {
            uint32_t a0, a1, a2, a3;
            LDSM_X4(a0, a1, a2, a3, abase + ks * 32);
#pragma unroll
            for (int p = 0; p < 8; p++) {
                uint32_t b0, b1, b2, b3;
                LDSM_X4(b0, b1, b2, b3, bbase + p * (16 * ROW_B) + ks * 32);
                MMA_BF16(acc[2 * p][0], acc[2 * p][1], acc[2 * p][2], acc[2 * p][3],
                         a0, a1, a2, a3, b0, b1);
                MMA_BF16(acc[2 * p + 1][0], acc[2 * p + 1][1], acc[2 * p + 1][2], acc[2 * p + 1][3],
                         a0, a1, a2, a3, b2, b3);
            }
        }
    }

    // ---- Epilogue: D frag (c0,c1)=row g, cols 2q..2q+1 ; (c2,c3)=row g+8
    const int g = lid >> 2;
    const int q = lid & 3;
    const int m0 = row0 + wid * 16 + g;
    const int m1 = m0 + 8;
#pragma unroll
    for (int nb = 0; nb < 16; nb++) {
        int col = nb * 8 + q * 2;
        if (m0 < M) *(float2*)(Xt + (size_t)m0 * EMBED + col) = make_float2(acc[nb][0], acc[nb][1]);
        if (m1 < M) *(float2*)(Xt + (size_t)m1 * EMBED + col) = make_float2(acc[nb][2], acc[nb][3]);
    }
}

// ---------------------------------------------------------------------------
// SpMM + residual: out[r] = x[r] + sum_{e in row r} vals[e] * g_xt[cols[e]]
// One warp per row; lane owns a float4. Inner loop unrolled x4 for MLP.
// Optionally writes out0[r] = x[r] (fused layer-0 copy).
// ---------------------------------------------------------------------------
__global__ __launch_bounds__(256) void spmm_kernel(const float* __restrict__ x,
                                                   const int* __restrict__ cols,
                                                   const float* __restrict__ vals,
                                                   float* __restrict__ out,
                                                   float* __restrict__ out0,
                                                   int M) {
    int warp = (blockIdx.x * blockDim.x + threadIdx.x) >> 5;
    int lane = threadIdx.x & 31;
    if (warp >= M) return;
    int r = warp;
    int s = g_row_ptr[r];
    int e = g_row_ptr[r + 1];

    float4 acc = make_float4(0.f, 0.f, 0.f, 0.f);
    for (int base = s; base < e; base += 32) {
        int idx = base + lane;
        int   c = 0;
        float v = 0.f;
        if (idx < e) { c = __ldg(cols + idx); v = __ldg(vals + idx); }
        int cnt = min(32, e - base);
        int j = 0;
        for (; j + 4 <= cnt; j += 4) {
            int   c0 = __shfl_sync(0xffffffffu, c, j);
            int   c1 = __shfl_sync(0xffffffffu, c, j + 1);
            int   c2 = __shfl_sync(0xffffffffu, c, j + 2);
            int   c3 = __shfl_sync(0xffffffffu, c, j + 3);
            float v0 = __shfl_sync(0xffffffffu, v, j);
            float v1 = __shfl_sync(0xffffffffu, v, j + 1);
            float v2 = __shfl_sync(0xffffffffu, v, j + 2);
            float v3 = __shfl_sync(0xffffffffu, v, j + 3);
            float4 t0 = ((const float4*)(g_xt + (size_t)c0 * EMBED))[lane];
            float4 t1 = ((const float4*)(g_xt + (size_t)c1 * EMBED))[lane];
            float4 t2 = ((const float4*)(g_xt + (size_t)c2 * EMBED))[lane];
            float4 t3 = ((const float4*)(g_xt + (size_t)c3 * EMBED))[lane];
            acc.x += v0 * t0.x; acc.y += v0 * t0.y; acc.z += v0 * t0.z; acc.w += v0 * t0.w;
            acc.x += v1 * t1.x; acc.y += v1 * t1.y; acc.z += v1 * t1.z; acc.w += v1 * t1.w;
            acc.x += v2 * t2.x; acc.y += v2 * t2.y; acc.z += v2 * t2.z; acc.w += v2 * t2.w;
            acc.x += v3 * t3.x; acc.y += v3 * t3.y; acc.z += v3 * t3.z; acc.w += v3 * t3.w;
        }
        for (; j < cnt; j++) {
            int   cj = __shfl_sync(0xffffffffu, c, j);
            float vj = __shfl_sync(0xffffffffu, v, j);
            float4 t4 = ((const float4*)(g_xt + (size_t)cj * EMBED))[lane];
            acc.x += vj * t4.x; acc.y += vj * t4.y; acc.z += vj * t4.z; acc.w += vj * t4.w;
        }
    }
    float4 xv = ((const float4*)(x + (size_t)r * EMBED))[lane];
    if (out0) ((float4*)(out0 + (size_t)r * EMBED))[lane] = xv;
    acc.x += xv.x; acc.y += xv.y; acc.z += xv.z; acc.w += xv.w;
    ((float4*)(out + (size_t)r * EMBED))[lane] = acc;
}

// ---------------------------------------------------------------------------
// kernel_launch
// ---------------------------------------------------------------------------
extern "C" void kernel_launch(void* const* d_in, const int* in_sizes, int n_in,
                              void* d_out, int out_size) {
    const float* ue   = (const float*)d_in[0];
    const int*   rows = (const int*)  d_in[1];
    const int*   cols = (const int*)  d_in[2];
    const float* vals = (const float*)d_in[3];
    const float* W0   = (const float*)d_in[4];
    const float* W1   = (const float*)d_in[5];
    float* out = (float*)d_out;

    const int M = in_sizes[0] / EMBED;
    const int E = in_sizes[1];
    const size_t layer_elems = (size_t)M * EMBED;

    float* xt_ptr;
    cudaGetSymbolAddress((void**)&xt_ptr, g_xt);

    cudaFuncSetAttribute(gemm_hmma_kernel, cudaFuncAttributeMaxDynamicSharedMemorySize, SM_TOTAL);

    prep_w_kernel<<<2, 256>>>(W0, W1);
    build_rowptr_kernel<<<(E + 255) / 256, 256>>>(rows, E, M);

    const int gemm_blocks = (M + TILE_M - 1) / TILE_M;
    const int spmm_blocks = (M * 32 + 255) / 256;

    // Layer 1 (SpMM also emits out[0] = user_embeds)
    gemm_hmma_kernel<<<gemm_blocks, 256, SM_TOTAL>>>(ue, 0, xt_ptr, M);
    spmm_kernel<<<spmm_blocks, 256>>>(ue, cols, vals, out + layer_elems, out, M);

    // Layer 2
    gemm_hmma_kernel<<<gemm_blocks, 256, SM_TOTAL>>>(out + layer_elems, 1, xt_ptr, M);
    spmm_kernel<<<spmm_blocks, 256>>>(out + layer_elems, cols, vals,
                                      out + 2 * layer_elems, nullptr, M);
}

// round 5
// speedup vs baseline: 1.0248x; 1.0248x over previous
#include <cuda_runtime.h>
#include <cuda_bf16.h>
#include <stdint.h>

#define MAX_USERS 100000
#define EMBED 128
#define TILE_M 64            // rows per GEMM CTA

// ---------------------------------------------------------------------------
// Scratch in __device__ globals (no allocation allowed anywhere)
// ---------------------------------------------------------------------------
__device__ float    g_xt[(size_t)MAX_USERS * EMBED];  // x @ W result
__device__ int      g_row_ptr[MAX_USERS + 1];
__device__ uint16_t g_wt[2][2][EMBED * EMBED];        // [layer][hi/lo] W^T bf16, [n][k]

// ---------------------------------------------------------------------------
// SMEM: xh(16K) | xl(16K) | wh(32K) | wl(32K) = 96KB -> 2 CTAs/SM
// Rows are 256B (128 bf16); swizzle: addr = row*256 + (kb ^ ((row&7)<<4))
// -> LDSM (8 rows x 16B) hits 8 distinct 16B groups; 16B stores stay aligned.
// ---------------------------------------------------------------------------
#define SM_XH 0
#define SM_XL 16384
#define SM_WH 32768
#define SM_WL 65536
#define SM_TOTAL 98304

__device__ __forceinline__ uint32_t smem_u32(const void* p) {
    uint32_t a;
    asm("{ .reg .u64 t; cvta.to.shared.u64 t, %1; cvt.u32.u64 %0, t; }" : "=r"(a) : "l"(p));
    return a;
}

#define LDSM_X4(f0, f1, f2, f3, addr) \
    asm volatile("ldmatrix.sync.aligned.m8n8.x4.shared.b16 {%0,%1,%2,%3}, [%4];" \
        : "=r"(f0), "=r"(f1), "=r"(f2), "=r"(f3) : "r"(addr))

#define MMA_BF16(c0, c1, c2, c3, a0, a1, a2, a3, b0, b1) \
    asm volatile("mma.sync.aligned.m16n8k16.row.col.f32.bf16.bf16.f32 " \
        "{%0,%1,%2,%3}, {%4,%5,%6,%7}, {%8,%9}, {%0,%1,%2,%3};" \
        : "+f"(c0), "+f"(c1), "+f"(c2), "+f"(c3) \
        : "r"(a0), "r"(a1), "r"(a2), "r"(a3), "r"(b0), "r"(b1))

// ---------------------------------------------------------------------------
// Prep: W (row-major [k][n]) -> W^T bf16 hi/lo planes in [n][k] order
// ---------------------------------------------------------------------------
__global__ void prep_w_kernel(const float* __restrict__ W0, const float* __restrict__ W1) {
    const float* W = (blockIdx.x == 0) ? W0 : W1;
    uint16_t* dh = g_wt[blockIdx.x][0];
    uint16_t* dl = g_wt[blockIdx.x][1];
    for (int idx = threadIdx.x; idx < EMBED * EMBED; idx += blockDim.x) {
        int k = idx >> 7, n = idx & 127;
        float w = W[idx];
        __nv_bfloat16 h = __float2bfloat16(w);
        __nv_bfloat16 l = __float2bfloat16(w - __bfloat162float(h));
        dh[n * EMBED + k] = *(uint16_t*)&h;
        dl[n * EMBED + k] = *(uint16_t*)&l;
    }
}

// ---------------------------------------------------------------------------
// Build CSR row_ptr from sorted s_rows
// ---------------------------------------------------------------------------
__global__ void build_rowptr_kernel(const int* __restrict__ rows, int E, int M) {
    int e = blockIdx.x * blockDim.x + threadIdx.x;
    if (e >= E) return;
    int r = rows[e];
    if (e == 0) { for (int i = 0; i <= r; i++) g_row_ptr[i] = 0; }
    else { int rp = rows[e - 1]; for (int i = rp + 1; i <= r; i++) g_row_ptr[i] = e; }
    if (e == E - 1) { for (int i = r + 1; i <= M; i++) g_row_ptr[i] = E; }
}

// ---------------------------------------------------------------------------
// HMMA GEMM, latency-optimized: 64-row tile, 96KB smem, 2 CTAs/SM.
// Warp w: rows (w>>1)*16..+15, cols (w&1)*64..+63. 3-product bf16 split.
// ---------------------------------------------------------------------------
__global__ __launch_bounds__(256, 2) void gemm_hmma_kernel(const float* __restrict__ A,
                                                           int layer,
                                                           float* __restrict__ Xt,
                                                           int M) {
    extern __shared__ char smem[];
    const uint32_t sb = smem_u32(smem);
    const int tid = threadIdx.x;
    const int wid = tid >> 5;
    const int lid = tid & 31;
    const int row0 = blockIdx.x * TILE_M;

    // ---- Stage W^T hi/lo (swizzled): thread t -> n = t>>1, 128B half h = t&1
    {
        const uint4* gh = (const uint4*)g_wt[layer][0];
        const uint4* gl = (const uint4*)g_wt[layer][1];
        int n = tid >> 1, h = tid & 1;
        uint32_t nsw = (uint32_t)((n & 7) << 4);
        uint32_t rbase = (uint32_t)(n * 256);
#pragma unroll
        for (int c = 0; c < 8; c++) {
            uint32_t kb = (uint32_t)(h * 128 + c * 16);
            uint32_t off = rbase + (kb ^ nsw);
            *(uint4*)(smem + SM_WH + off) = gh[n * 16 + h * 8 + c];
            *(uint4*)(smem + SM_WL + off) = gl[n * 16 + h * 8 + c];
        }
    }

    // ---- Stage A rows -> bf16 hi/lo (swizzled): thread t -> row t>>2, quarter t&3
    {
        int r = tid >> 2, q = tid & 3;           // quarter = 32 k-elements
        int grow = row0 + r;
        const float4* src = (grow < M) ? (const float4*)(A + (size_t)grow * EMBED + q * 32) : nullptr;
        uint32_t rsw = (uint32_t)((r & 7) << 4);
        uint32_t rbase = (uint32_t)(r * 256);
#pragma unroll
        for (int c = 0; c < 4; c++) {            // 4 x 16B chunks (8 bf16 each)
            uint32_t hp[4], lp[4];
#pragma unroll
            for (int i = 0; i < 2; i++) {
                float4 f = src ? src[c * 2 + i] : make_float4(0.f, 0.f, 0.f, 0.f);
                __nv_bfloat16 h0 = __float2bfloat16(f.x), h1 = __float2bfloat16(f.y);
                __nv_bfloat16 h2 = __float2bfloat16(f.z), h3 = __float2bfloat16(f.w);
                __nv_bfloat16 l0 = __float2bfloat16(f.x - __bfloat162float(h0));
                __nv_bfloat16 l1 = __float2bfloat16(f.y - __bfloat162float(h1));
                __nv_bfloat16 l2 = __float2bfloat16(f.z - __bfloat162float(h2));
                __nv_bfloat16 l3 = __float2bfloat16(f.w - __bfloat162float(h3));
                hp[2 * i]     = (uint32_t)*(uint16_t*)&h0 | ((uint32_t)*(uint16_t*)&h1 << 16);
                hp[2 * i + 1] = (uint32_t)*(uint16_t*)&h2 | ((uint32_t)*(uint16_t*)&h3 << 16);
                lp[2 * i]     = (uint32_t)*(uint16_t*)&l0 | ((uint32_t)*(uint16_t*)&l1 << 16);
                lp[2 * i + 1] = (uint32_t)*(uint16_t*)&l2 | ((uint32_t)*(uint16_t*)&l3 << 16);
            }
            uint32_t kb = (uint32_t)(q * 64 + c * 16);
            uint32_t off = rbase + (kb ^ rsw);
            *(uint4*)(smem + SM_XH + off) = make_uint4(hp[0], hp[1], hp[2], hp[3]);
            *(uint4*)(smem + SM_XL + off) = make_uint4(lp[0], lp[1], lp[2], lp[3]);
        }
    }
    __syncthreads();

    // ---- Fragment addressing (mappings identical to R4, which verified correct)
    const int ch = wid & 1;                 // col half: cols ch*64..+63
    const int rg = wid >> 1;                // row group: rows rg*16..+15
    const uint32_t lsw = (uint32_t)((lid & 7) << 4);   // swizzle term, lane-constant

    const int a_m = (((lid >> 3) & 1) << 3) + (lid & 7);
    const uint32_t a_kb0 = (uint32_t)((((lid >> 4) & 1) << 3) * 2);
    const uint32_t a_rbase = (uint32_t)((rg * 16 + a_m) * 256);

    const int b_nl = (((lid >> 4) & 1) << 3) + (lid & 7);
    const uint32_t b_kb0 = (uint32_t)((((lid >> 3) & 1) << 3) * 2);
    const uint32_t b_rbase0 = (uint32_t)((ch * 64 + b_nl) * 256);

    float acc[8][4];
#pragma unroll
    for (int nb = 0; nb < 8; nb++)
#pragma unroll
        for (int i = 0; i < 4; i++) acc[nb][i] = 0.f;

#pragma unroll
    for (int ks = 0; ks < 8; ks++) {
        const uint32_t akb = (a_kb0 + (uint32_t)(ks * 32)) ^ lsw;
        const uint32_t bkb = (b_kb0 + (uint32_t)(ks * 32)) ^ lsw;
        uint32_t ah0, ah1, ah2, ah3, al0, al1, al2, al3;
        LDSM_X4(ah0, ah1, ah2, ah3, sb + SM_XH + a_rbase + akb);
        LDSM_X4(al0, al1, al2, al3, sb + SM_XL + a_rbase + akb);
#pragma unroll
        for (int p = 0; p < 4; p++) {
            const uint32_t brow = b_rbase0 + (uint32_t)(p * 16 * 256);
            uint32_t bh0, bh1, bh2, bh3, bl0, bl1, bl2, bl3;
            LDSM_X4(bh0, bh1, bh2, bh3, sb + SM_WH + brow + bkb);
            LDSM_X4(bl0, bl1, bl2, bl3, sb + SM_WL + brow + bkb);
            float* c0 = acc[2 * p];
            float* c1 = acc[2 * p + 1];
            MMA_BF16(c0[0], c0[1], c0[2], c0[3], ah0, ah1, ah2, ah3, bh0, bh1);
            MMA_BF16(c1[0], c1[1], c1[2], c1[3], ah0, ah1, ah2, ah3, bh2, bh3);
            MMA_BF16(c0[0], c0[1], c0[2], c0[3], ah0, ah1, ah2, ah3, bl0, bl1);
            MMA_BF16(c1[0], c1[1], c1[2], c1[3], ah0, ah1, ah2, ah3, bl2, bl3);
            MMA_BF16(c0[0], c0[1], c0[2], c0[3], al0, al1, al2, al3, bh0, bh1);
            MMA_BF16(c1[0], c1[1], c1[2], c1[3], al0, al1, al2, al3, bh2, bh3);
        }
    }

    // ---- Epilogue: (c0,c1)=row g cols 2q..2q+1 ; (c2,c3)=row g+8
    const int g = lid >> 2;
    const int q = lid & 3;
    const int m0 = row0 + rg * 16 + g;
    const int m1 = m0 + 8;
#pragma unroll
    for (int nb = 0; nb < 8; nb++) {
        int col = ch * 64 + nb * 8 + q * 2;
        if (m0 < M) *(float2*)(Xt + (size_t)m0 * EMBED + col) = make_float2(acc[nb][0], acc[nb][1]);
        if (m1 < M) *(float2*)(Xt + (size_t)m1 * EMBED + col) = make_float2(acc[nb][2], acc[nb][3]);
    }
}

// ---------------------------------------------------------------------------
// SpMM + residual — exact R1 structure (proven 72.6us, at L2 roofline).
// One warp per row; lane owns a float4; serial shfl-broadcast loop.
// ---------------------------------------------------------------------------
__global__ __launch_bounds__(256) void spmm_kernel(const float* __restrict__ x,
                                                   const int* __restrict__ cols,
                                                   const float* __restrict__ vals,
                                                   float* __restrict__ out,
                                                   float* __restrict__ out0,
                                                   int M) {
    int warp = (blockIdx.x * blockDim.x + threadIdx.x) >> 5;
    int lane = threadIdx.x & 31;
    if (warp >= M) return;
    int r = warp;
    int s = g_row_ptr[r];
    int e = g_row_ptr[r + 1];

    float4 acc = make_float4(0.f, 0.f, 0.f, 0.f);
    for (int base = s; base < e; base += 32) {
        int idx = base + lane;
        int   c = 0;
        float v = 0.f;
        if (idx < e) { c = __ldg(cols + idx); v = __ldg(vals + idx); }
        int cnt = min(32, e - base);
        for (int j = 0; j < cnt; j++) {
            int   cj = __shfl_sync(0xffffffffu, c, j);
            float vj = __shfl_sync(0xffffffffu, v, j);
            float4 t4 = ((const float4*)(g_xt + (size_t)cj * EMBED))[lane];
            acc.x += vj * t4.x;
            acc.y += vj * t4.y;
            acc.z += vj * t4.z;
            acc.w += vj * t4.w;
        }
    }
    float4 xv = ((const float4*)(x + (size_t)r * EMBED))[lane];
    if (out0) ((float4*)(out0 + (size_t)r * EMBED))[lane] = xv;
    acc.x += xv.x; acc.y += xv.y; acc.z += xv.z; acc.w += xv.w;
    ((float4*)(out + (size_t)r * EMBED))[lane] = acc;
}

// ---------------------------------------------------------------------------
// kernel_launch
// ---------------------------------------------------------------------------
extern "C" void kernel_launch(void* const* d_in, const int* in_sizes, int n_in,
                              void* d_out, int out_size) {
    const float* ue   = (const float*)d_in[0];
    const int*   rows = (const int*)  d_in[1];
    const int*   cols = (const int*)  d_in[2];
    const float* vals = (const float*)d_in[3];
    const float* W0   = (const float*)d_in[4];
    const float* W1   = (const float*)d_in[5];
    float* out = (float*)d_out;

    const int M = in_sizes[0] / EMBED;
    const int E = in_sizes[1];
    const size_t layer_elems = (size_t)M * EMBED;

    float* xt_ptr;
    cudaGetSymbolAddress((void**)&xt_ptr, g_xt);

    cudaFuncSetAttribute(gemm_hmma_kernel, cudaFuncAttributeMaxDynamicSharedMemorySize, SM_TOTAL);

    prep_w_kernel<<<2, 256>>>(W0, W1);
    build_rowptr_kernel<<<(E + 255) / 256, 256>>>(rows, E, M);

    const int gemm_blocks = (M + TILE_M - 1) / TILE_M;
    const int spmm_blocks = (M * 32 + 255) / 256;

    // Layer 1 (SpMM also emits out[0] = user_embeds)
    gemm_hmma_kernel<<<gemm_blocks, 256, SM_TOTAL>>>(ue, 0, xt_ptr, M);
    spmm_kernel<<<spmm_blocks, 256>>>(ue, cols, vals, out + layer_elems, out, M);

    // Layer 2
    gemm_hmma_kernel<<<gemm_blocks, 256, SM_TOTAL>>>(out + layer_elems, 1, xt_ptr, M);
    spmm_kernel<<<spmm_blocks, 256>>>(out + layer_elems, cols, vals,
                                      out + 2 * layer_elems, nullptr, M);
}

// round 6
// speedup vs baseline: 1.0988x; 1.0721x over previous
#include <cuda_runtime.h>
#include <cuda_bf16.h>
#include <stdint.h>

#define MAX_USERS 100000
#define EMBED 128
#define TILE_M 64            // rows per GEMM CTA

// ---------------------------------------------------------------------------
// Scratch in __device__ globals (no allocation allowed anywhere)
// ---------------------------------------------------------------------------
__device__ float    g_xt[(size_t)MAX_USERS * EMBED];  // x @ W result
__device__ int      g_row_ptr[MAX_USERS + 1];
__device__ uint32_t g_wt32[2][EMBED * EMBED];         // [layer] W^T in tf32 bits, [n][k]

// ---------------------------------------------------------------------------
// SMEM: A (64 x 132 fp32/tf32) | W^T (128 x 132 tf32). Padded stride 132 floats
// (528 B): 132 mod 32 = 4 -> row r starts at bank 4r mod 32 -> all frag LDS.32
// patterns (4 lanes/row x 8 rows) hit 32 distinct banks.
// ---------------------------------------------------------------------------
#define ROWF 132
#define ROWB (ROWF * 4)                  // 528
#define SM_A 0
#define SM_W (TILE_M * ROWB)             // 33792
#define SM_TOTAL (SM_W + EMBED * ROWB)   // 33792 + 67584 = 101376

__device__ __forceinline__ uint32_t cvt_tf32(float f) {
    uint32_t u;
    asm("cvt.rna.tf32.f32 %0, %1;" : "=r"(u) : "f"(f));
    return u;
}

#define MMA_TF32(c0, c1, c2, c3, a0, a1, a2, a3, b0, b1) \
    asm volatile("mma.sync.aligned.m16n8k8.row.col.f32.tf32.tf32.f32 " \
        "{%0,%1,%2,%3}, {%4,%5,%6,%7}, {%8,%9}, {%0,%1,%2,%3};" \
        : "+f"(c0), "+f"(c1), "+f"(c2), "+f"(c3) \
        : "r"(a0), "r"(a1), "r"(a2), "r"(a3), "r"(b0), "r"(b1))

// ---------------------------------------------------------------------------
// Prep: W (row-major [k][n]) -> W^T tf32 bits in [n][k] order. 64 blocks/layer.
// ---------------------------------------------------------------------------
__global__ void prep_w_kernel(const float* __restrict__ W0, const float* __restrict__ W1) {
    int layer = blockIdx.x >> 6;
    int idx = (blockIdx.x & 63) * 256 + threadIdx.x;   // 0..16383
    const float* W = layer ? W1 : W0;
    int k = idx >> 7, n = idx & 127;
    g_wt32[layer][n * EMBED + k] = cvt_tf32(W[idx]);
}

// ---------------------------------------------------------------------------
// Build CSR row_ptr from sorted s_rows
// ---------------------------------------------------------------------------
__global__ void build_rowptr_kernel(const int* __restrict__ rows, int E, int M) {
    int e = blockIdx.x * blockDim.x + threadIdx.x;
    if (e >= E) return;
    int r = rows[e];
    if (e == 0) { for (int i = 0; i <= r; i++) g_row_ptr[i] = 0; }
    else { int rp = rows[e - 1]; for (int i = rp + 1; i <= r; i++) g_row_ptr[i] = e; }
    if (e == E - 1) { for (int i = r + 1; i <= M; i++) g_row_ptr[i] = E; }
}

// ---------------------------------------------------------------------------
// tf32 GEMM: Xt = A[M,128] @ W[128,128], single product (err ~1e-4 << 1e-3).
// CTA: 256 threads / 8 warps; warp (rg,ch): rows rg*16..+15, cols ch*64..+63.
// ---------------------------------------------------------------------------
__global__ __launch_bounds__(256, 2) void gemm_tf32_kernel(const float* __restrict__ A,
                                                           int layer,
                                                           float* __restrict__ Xt,
                                                           int M) {
    extern __shared__ char smem[];
    const int tid = threadIdx.x;
    const int wid = tid >> 5;
    const int lid = tid & 31;
    const int row0 = blockIdx.x * TILE_M;

    // ---- Stage W^T (tf32 bits): thread -> (n = tid&127, half h = tid>>7)
    {
        int n = tid & 127, h = tid >> 7;
        const uint4* src = (const uint4*)(g_wt32[layer] + n * EMBED + h * 64);
        uint4* dst = (uint4*)(smem + SM_W + n * ROWB + h * 256);
#pragma unroll
        for (int c = 0; c < 16; c++) dst[c] = src[c];
    }

    // ---- Stage A rows -> tf32: thread -> (r = tid&63, quarter q = tid>>6)
    {
        int r = tid & 63, q = tid >> 6;
        int grow = row0 + r;
        const float4* src = (grow < M) ? (const float4*)(A + (size_t)grow * EMBED + q * 32) : nullptr;
        uint4* dst = (uint4*)(smem + SM_A + r * ROWB + q * 128);
#pragma unroll
        for (int c = 0; c < 8; c++) {
            float4 f = src ? src[c] : make_float4(0.f, 0.f, 0.f, 0.f);
            dst[c] = make_uint4(cvt_tf32(f.x), cvt_tf32(f.y), cvt_tf32(f.z), cvt_tf32(f.w));
        }
    }
    __syncthreads();

    // ---- Fragment addressing (m16n8k8: g = lid>>2 row/n-group, tg = lid&3 k)
    const int rg = wid >> 1;               // row group: rows rg*16..+15
    const int ch = wid & 1;                // col half: cols ch*64..+63
    const int g  = lid >> 2;
    const int tg = lid & 3;

    const char* Abase = smem + SM_A + (rg * 16 + g) * ROWB + tg * 4;
    const char* Bbase = smem + SM_W + (ch * 64 + g) * ROWB + tg * 4;

    float acc[8][4];
#pragma unroll
    for (int nb = 0; nb < 8; nb++)
#pragma unroll
        for (int i = 0; i < 4; i++) acc[nb][i] = 0.f;

#pragma unroll
    for (int ks = 0; ks < 16; ks++) {
        const int ko = ks * 32;            // 8 k-floats = 32 bytes
        uint32_t a0 = *(const uint32_t*)(Abase + ko);
        uint32_t a1 = *(const uint32_t*)(Abase + 8 * ROWB + ko);
        uint32_t a2 = *(const uint32_t*)(Abase + ko + 16);
        uint32_t a3 = *(const uint32_t*)(Abase + 8 * ROWB + ko + 16);
#pragma unroll
        for (int p = 0; p < 8; p++) {
            const char* Bp = Bbase + p * 8 * ROWB;
            uint32_t b0 = *(const uint32_t*)(Bp + ko);
            uint32_t b1 = *(const uint32_t*)(Bp + ko + 16);
            MMA_TF32(acc[p][0], acc[p][1], acc[p][2], acc[p][3], a0, a1, a2, a3, b0, b1);
        }
    }

    // ---- Epilogue: (c0,c1)=row rg*16+g cols 2tg..+1 ; (c2,c3)=row +8
    const int m0 = row0 + rg * 16 + g;
    const int m1 = m0 + 8;
#pragma unroll
    for (int nb = 0; nb < 8; nb++) {
        int col = ch * 64 + nb * 8 + tg * 2;
        if (m0 < M) *(float2*)(Xt + (size_t)m0 * EMBED + col) = make_float2(acc[nb][0], acc[nb][1]);
        if (m1 < M) *(float2*)(Xt + (size_t)m1 * EMBED + col) = make_float2(acc[nb][2], acc[nb][3]);
    }
}

// ---------------------------------------------------------------------------
// SpMM + residual — R1 structure (at L2 roofline). out0 fuses layer-0 copy.
// ---------------------------------------------------------------------------
__global__ __launch_bounds__(256) void spmm_kernel(const float* __restrict__ x,
                                                   const int* __restrict__ cols,
                                                   const float* __restrict__ vals,
                                                   float* __restrict__ out,
                                                   float* __restrict__ out0,
                                                   int M) {
    int warp = (blockIdx.x * blockDim.x + threadIdx.x) >> 5;
    int lane = threadIdx.x & 31;
    if (warp >= M) return;
    int r = warp;
    int s = g_row_ptr[r];
    int e = g_row_ptr[r + 1];

    float4 acc = make_float4(0.f, 0.f, 0.f, 0.f);
    for (int base = s; base < e; base += 32) {
        int idx = base + lane;
        int   c = 0;
        float v = 0.f;
        if (idx < e) { c = __ldg(cols + idx); v = __ldg(vals + idx); }
        int cnt = min(32, e - base);
        for (int j = 0; j < cnt; j++) {
            int   cj = __shfl_sync(0xffffffffu, c, j);
            float vj = __shfl_sync(0xffffffffu, v, j);
            float4 t4 = ((const float4*)(g_xt + (size_t)cj * EMBED))[lane];
            acc.x += vj * t4.x;
            acc.y += vj * t4.y;
            acc.z += vj * t4.z;
            acc.w += vj * t4.w;
        }
    }
    float4 xv = ((const float4*)(x + (size_t)r * EMBED))[lane];
    if (out0) ((float4*)(out0 + (size_t)r * EMBED))[lane] = xv;
    acc.x += xv.x; acc.y += xv.y; acc.z += xv.z; acc.w += xv.w;
    ((float4*)(out + (size_t)r * EMBED))[lane] = acc;
}

// ---------------------------------------------------------------------------
// kernel_launch
// ---------------------------------------------------------------------------
extern "C" void kernel_launch(void* const* d_in, const int* in_sizes, int n_in,
                              void* d_out, int out_size) {
    const float* ue   = (const float*)d_in[0];
    const int*   rows = (const int*)  d_in[1];
    const int*   cols = (const int*)  d_in[2];
    const float* vals = (const float*)d_in[3];
    const float* W0   = (const float*)d_in[4];
    const float* W1   = (const float*)d_in[5];
    float* out = (float*)d_out;

    const int M = in_sizes[0] / EMBED;
    const int E = in_sizes[1];
    const size_t layer_elems = (size_t)M * EMBED;

    float* xt_ptr;
    cudaGetSymbolAddress((void**)&xt_ptr, g_xt);

    cudaFuncSetAttribute(gemm_tf32_kernel, cudaFuncAttributeMaxDynamicSharedMemorySize, SM_TOTAL);

    prep_w_kernel<<<128, 256>>>(W0, W1);
    build_rowptr_kernel<<<(E + 255) / 256, 256>>>(rows, E, M);

    const int gemm_blocks = (M + TILE_M - 1) / TILE_M;
    const int spmm_blocks = (M * 32 + 255) / 256;

    // Layer 1 (SpMM also emits out[0] = user_embeds)
    gemm_tf32_kernel<<<gemm_blocks, 256, SM_TOTAL>>>(ue, 0, xt_ptr, M);
    spmm_kernel<<<spmm_blocks, 256>>>(ue, cols, vals, out + layer_elems, out, M);

    // Layer 2
    gemm_tf32_kernel<<<gemm_blocks, 256, SM_TOTAL>>>(out + layer_elems, 1, xt_ptr, M);
    spmm_kernel<<<spmm_blocks, 256>>>(out + layer_elems, cols, vals,
                                      out + 2 * layer_elems, nullptr, M);
}